// round 5
// baseline (speedup 1.0000x reference)
#include <cuda_runtime.h>
#include <stdint.h>

// Problem-size constants (match reference: N=1e6, E=5e6, EL=2e6, D=F=16)
#define NN 1000000
#define NE 5000000
#define NEL 2000000

// ---------------------------------------------------------------------------
// Static scratch (allocation-free rule: __device__ globals)
// ---------------------------------------------------------------------------
__device__ float  d_deg [NN];        // 4 MB
__device__ float  d_dinv[NN];        // 4 MB
__device__ float4 d_g   [NN * 4];    // 64 MB  : g = dinv * (h @ W)
__device__ float4 d_acc [NN * 4];    // 64 MB  : neighbor accumulator (incl. self)
__device__ float2 d_zfc [NN];        // 8 MB   : (z . fcw[:16], z . fcw[16:32])

// ---------------------------------------------------------------------------
// Degree
// ---------------------------------------------------------------------------
__global__ void k_deg_init(int n) {
    int i = blockIdx.x * blockDim.x + threadIdx.x;
    if (i < n) d_deg[i] = 1.0f;   // self-loop
}

__global__ void k_deg_edges(const int* __restrict__ dst, int e) {
    int i = blockIdx.x * blockDim.x + threadIdx.x;
    if (i < e) atomicAdd(&d_deg[__ldg(dst + i)], 1.0f);
}

// ---------------------------------------------------------------------------
// Layer 1 node kernel: dinv = rsqrt(deg); h = embed[x]; g = dinv*(h@W1);
// acc = g (self-loop term)
// ---------------------------------------------------------------------------
__global__ void k_layer1(const int* __restrict__ x,
                         const float4* __restrict__ embed4,
                         const float* __restrict__ W1, int n) {
    __shared__ float Ws[256];
    int t = threadIdx.x;
    if (t < 64) ((float4*)Ws)[t] = ((const float4*)W1)[t];
    __syncthreads();

    int i = blockIdx.x * blockDim.x + t;
    if (i >= n) return;

    float dv = rsqrtf(d_deg[i]);
    d_dinv[i] = dv;

    int xi = __ldg(x + i);
    float h[16];
#pragma unroll
    for (int q = 0; q < 4; q++) {
        float4 v = embed4[(size_t)xi * 4 + q];
        h[4 * q + 0] = v.x; h[4 * q + 1] = v.y;
        h[4 * q + 2] = v.z; h[4 * q + 3] = v.w;
    }

    float acc[16];
#pragma unroll
    for (int j = 0; j < 16; j++) acc[j] = 0.0f;
#pragma unroll
    for (int k = 0; k < 16; k++) {
        float hk = h[k];
#pragma unroll
        for (int j = 0; j < 16; j++) acc[j] = fmaf(hk, Ws[k * 16 + j], acc[j]);
    }

#pragma unroll
    for (int q = 0; q < 4; q++) {
        float4 o = make_float4(dv * acc[4 * q + 0], dv * acc[4 * q + 1],
                               dv * acc[4 * q + 2], dv * acc[4 * q + 3]);
        d_g[(size_t)i * 4 + q]   = o;
        d_acc[(size_t)i * 4 + q] = o;
    }
}

// ---------------------------------------------------------------------------
// Edge scatter: acc[dst] += g[src]   (4 threads per edge, red.v4.f32)
// ---------------------------------------------------------------------------
__global__ void k_scatter(const int* __restrict__ src,
                          const int* __restrict__ dst, int e) {
    int gid = blockIdx.x * blockDim.x + threadIdx.x;
    int ei = gid >> 2;
    if (ei >= e) return;
    int j = gid & 3;
    int s  = __ldg(src + ei);
    int d0 = __ldg(dst + ei);
    float4 v = d_g[(size_t)s * 4 + j];
    float4* p = &d_acc[(size_t)d0 * 4 + j];
    asm volatile("red.global.add.v4.f32 [%0], {%1, %2, %3, %4};"
                 :: "l"(p), "f"(v.x), "f"(v.y), "f"(v.z), "f"(v.w)
                 : "memory");
}

// ---------------------------------------------------------------------------
// Layer 2 node kernel (fuses layer-1 epilogue):
//   h1 = relu(dinv*acc1 + b1); g2 = dinv*(h1@W2); acc2 = g2
// ---------------------------------------------------------------------------
__global__ void k_layer2(const float* __restrict__ b1,
                         const float* __restrict__ W2, int n) {
    __shared__ float Ws[256];
    __shared__ float bs[16];
    int t = threadIdx.x;
    if (t < 64) ((float4*)Ws)[t] = ((const float4*)W2)[t];
    if (t < 16) bs[t] = b1[t];
    __syncthreads();

    int i = blockIdx.x * blockDim.x + t;
    if (i >= n) return;

    float dv = d_dinv[i];
    float h[16];
#pragma unroll
    for (int q = 0; q < 4; q++) {
        float4 a = d_acc[(size_t)i * 4 + q];
        h[4 * q + 0] = fmaxf(fmaf(dv, a.x, bs[4 * q + 0]), 0.0f);
        h[4 * q + 1] = fmaxf(fmaf(dv, a.y, bs[4 * q + 1]), 0.0f);
        h[4 * q + 2] = fmaxf(fmaf(dv, a.z, bs[4 * q + 2]), 0.0f);
        h[4 * q + 3] = fmaxf(fmaf(dv, a.w, bs[4 * q + 3]), 0.0f);
    }

    float acc[16];
#pragma unroll
    for (int j = 0; j < 16; j++) acc[j] = 0.0f;
#pragma unroll
    for (int k = 0; k < 16; k++) {
        float hk = h[k];
#pragma unroll
        for (int j = 0; j < 16; j++) acc[j] = fmaf(hk, Ws[k * 16 + j], acc[j]);
    }

#pragma unroll
    for (int q = 0; q < 4; q++) {
        float4 o = make_float4(dv * acc[4 * q + 0], dv * acc[4 * q + 1],
                               dv * acc[4 * q + 2], dv * acc[4 * q + 3]);
        d_g[(size_t)i * 4 + q]   = o;
        d_acc[(size_t)i * 4 + q] = o;
    }
}

// ---------------------------------------------------------------------------
// Node epilogue: z = dinv*acc2 + b2; pre-fold fc weights:
//   zfc[i] = ( z . fcw[0:16], z . fcw[16:32] )
// ---------------------------------------------------------------------------
__global__ void k_node_out(const float* __restrict__ b2,
                           const float* __restrict__ fcw, int n) {
    __shared__ float bs[16];
    __shared__ float fw[32];
    int t = threadIdx.x;
    if (t < 16) bs[t] = b2[t];
    if (t < 32) fw[t] = fcw[t];
    __syncthreads();

    int i = blockIdx.x * blockDim.x + t;
    if (i >= n) return;

    float dv = d_dinv[i];
    float s0 = 0.0f, s1 = 0.0f;
#pragma unroll
    for (int q = 0; q < 4; q++) {
        float4 a = d_acc[(size_t)i * 4 + q];
        float z0 = fmaf(dv, a.x, bs[4 * q + 0]);
        float z1 = fmaf(dv, a.y, bs[4 * q + 1]);
        float z2 = fmaf(dv, a.z, bs[4 * q + 2]);
        float z3 = fmaf(dv, a.w, bs[4 * q + 3]);
        s0 = fmaf(z0, fw[4 * q + 0], s0);
        s0 = fmaf(z1, fw[4 * q + 1], s0);
        s0 = fmaf(z2, fw[4 * q + 2], s0);
        s0 = fmaf(z3, fw[4 * q + 3], s0);
        s1 = fmaf(z0, fw[16 + 4 * q + 0], s1);
        s1 = fmaf(z1, fw[16 + 4 * q + 1], s1);
        s1 = fmaf(z2, fw[16 + 4 * q + 2], s1);
        s1 = fmaf(z3, fw[16 + 4 * q + 3], s1);
    }
    d_zfc[i] = make_float2(s0, s1);
}

// ---------------------------------------------------------------------------
// Link prediction: out[e] = zfc[src].x + zfc[dst].y + fc_b
// ---------------------------------------------------------------------------
__global__ void k_pred(const int* __restrict__ eli,
                       float* __restrict__ out,
                       const float* __restrict__ fcb, int el) {
    int e = blockIdx.x * blockDim.x + threadIdx.x;
    if (e >= el) return;
    int s  = __ldg(eli + e);
    int d0 = __ldg(eli + el + e);
    float2 a = d_zfc[s];
    float2 b = d_zfc[d0];
    out[e] = a.x + b.y + __ldg(fcb);
}

// ---------------------------------------------------------------------------
// Launch
// ---------------------------------------------------------------------------
extern "C" void kernel_launch(void* const* d_in, const int* in_sizes, int n_in,
                              void* d_out, int out_size) {
    const int*   x     = (const int*)  d_in[0];
    const int*   ei    = (const int*)  d_in[1];   // [2, E]
    const int*   eli   = (const int*)  d_in[2];   // [2, EL]
    const float* embed = (const float*)d_in[3];
    const float* W1    = (const float*)d_in[4];
    const float* b1    = (const float*)d_in[5];
    const float* W2    = (const float*)d_in[6];
    const float* b2    = (const float*)d_in[7];
    const float* fcw   = (const float*)d_in[8];
    const float* fcb   = (const float*)d_in[9];
    float* out = (float*)d_out;

    int n  = in_sizes[0];
    int e  = in_sizes[1] / 2;
    int el = in_sizes[2] / 2;

    const int T = 256;
    int gn  = (n  + T - 1) / T;
    int ge  = (e  + T - 1) / T;
    int ge4 = (4 * e + T - 1) / T;
    int gel = (el + T - 1) / T;

    const int* src = ei;
    const int* dst = ei + e;

    k_deg_init <<<gn,  T>>>(n);
    k_deg_edges<<<ge,  T>>>(dst, e);
    k_layer1   <<<gn,  T>>>(x, (const float4*)embed, W1, n);
    k_scatter  <<<ge4, T>>>(src, dst, e);
    k_layer2   <<<gn,  T>>>(b1, W2, n);
    k_scatter  <<<ge4, T>>>(src, dst, e);
    k_node_out <<<gn,  T>>>(b2, fcw, n);
    k_pred     <<<gel, T>>>(eli, out, fcb, el);
}